// round 7
// baseline (speedup 1.0000x reference)
#include <cuda_runtime.h>
#include <math.h>

#define B_    256
#define N_    1152
#define C_    10
#define IN_   8
#define KO_   160
#define NG_   8                    // n per slab
#define GRID_ 144                  // N_/NG_

// u fp32 [n][ko][b] (189 MB); partials g_p[144][ko][b]; xT [(n,i)][b]
__device__ float g_u[(size_t)N_ * KO_ * B_];
__device__ float g_p[(size_t)GRID_ * KO_ * B_];
__device__ float g_xT[(size_t)N_ * IN_ * B_];
__device__ float g_vT[KO_ * B_];
__device__ float g_bij[N_ * C_];
__device__ float g_dummy[32];

__global__ void noop_k() {}

// ---------------------------------------------------------------------------
// K0: transpose x[b][(n,i)] -> xT[(n,i)][b]. 32x32 tiles.
// ---------------------------------------------------------------------------
__global__ __launch_bounds__(256) void xpose(const float* __restrict__ x)
{
    __shared__ float tile[32][33];
    const int cb = blockIdx.x * 32, bb = blockIdx.y * 32;
    const int tx = threadIdx.x, ty = threadIdx.y;   // 32 x 8
#pragma unroll
    for (int k = 0; k < 4; k++)
        tile[ty + 8 * k][tx] = x[(size_t)(bb + ty + 8 * k) * (N_ * IN_) + cb + tx];
    __syncthreads();
#pragma unroll
    for (int k = 0; k < 4; k++)
        g_xT[(size_t)(cb + ty + 8 * k) * B_ + bb + tx] = tile[tx][ty + 8 * k];
}

// ---------------------------------------------------------------------------
// K1: u[n][ko][b] = sum_i W[n,ko,i]*x[b,n,i]  (vectorized over b), fused
// s0-partials. Grid (144 n-groups, 2 ko-halves); 512 thr = 64 bq x 8 kg.
// ---------------------------------------------------------------------------
__global__ __launch_bounds__(512, 1) void uhat_s0(const float* __restrict__ W)
{
    __shared__ float Ws[NG_ * 640];          // [nn][ko_local*8+i], 20 KB
    const int g = blockIdx.x, h = blockIdx.y;
    const int t = threadIdx.x;
    const int bq = t & 63, kg = t >> 6, b0 = bq * 4;
    const int n0 = g * NG_;

    for (int jj = t; jj < NG_ * 640; jj += 512) {
        const int nn = jj / 640, r = jj % 640;
        Ws[jj] = W[(size_t)(n0 + nn) * (KO_ * IN_) + h * 640 + r];
    }
    __syncthreads();

    float4 s0[10];
#pragma unroll
    for (int j = 0; j < 10; j++) s0[j] = make_float4(0.f, 0.f, 0.f, 0.f);

    for (int nn = 0; nn < NG_; nn++) {
        const int n = n0 + nn;
        float4 x4[IN_];
#pragma unroll
        for (int i = 0; i < IN_; i++)
            x4[i] = __ldg((const float4*)(g_xT + ((size_t)n * IN_ + i) * B_ + b0));

        float* up = g_u + ((size_t)n * KO_ + h * 80) * B_ + b0;
        const float* wn = Ws + nn * 640;
#pragma unroll
        for (int j = 0; j < 10; j++) {
            const int kol = kg + 8 * j;
            const float4 wa = *(const float4*)(wn + kol * 8);
            const float4 wb = *(const float4*)(wn + kol * 8 + 4);
            float4 u = make_float4(0.f, 0.f, 0.f, 0.f);
            u.x = fmaf(wa.x,x4[0].x,fmaf(wa.y,x4[1].x,fmaf(wa.z,x4[2].x,fmaf(wa.w,x4[3].x,fmaf(wb.x,x4[4].x,fmaf(wb.y,x4[5].x,fmaf(wb.z,x4[6].x,wb.w*x4[7].x)))))));
            u.y = fmaf(wa.x,x4[0].y,fmaf(wa.y,x4[1].y,fmaf(wa.z,x4[2].y,fmaf(wa.w,x4[3].y,fmaf(wb.x,x4[4].y,fmaf(wb.y,x4[5].y,fmaf(wb.z,x4[6].y,wb.w*x4[7].y)))))));
            u.z = fmaf(wa.x,x4[0].z,fmaf(wa.y,x4[1].z,fmaf(wa.z,x4[2].z,fmaf(wa.w,x4[3].z,fmaf(wb.x,x4[4].z,fmaf(wb.y,x4[5].z,fmaf(wb.z,x4[6].z,wb.w*x4[7].z)))))));
            u.w = fmaf(wa.x,x4[0].w,fmaf(wa.y,x4[1].w,fmaf(wa.z,x4[2].w,fmaf(wa.w,x4[3].w,fmaf(wb.x,x4[4].w,fmaf(wb.y,x4[5].w,fmaf(wb.z,x4[6].w,wb.w*x4[7].w)))))));
            *(float4*)(up + (size_t)kol * B_) = u;
            s0[j].x += u.x; s0[j].y += u.y; s0[j].z += u.z; s0[j].w += u.w;
        }
    }
    float* pp = g_p + ((size_t)g * KO_ + h * 80) * B_ + b0;
#pragma unroll
    for (int j = 0; j < 10; j++)
        *(float4*)(pp + (size_t)(kg + 8 * j) * B_) = s0[j];
}

// ---------------------------------------------------------------------------
// K2: reduce 144 slabs + scale + squash. Grid (160 ko, 4 b-quarters),
// 128 thr = 16 quads x 8 slab-groups (18 slabs each).
// ---------------------------------------------------------------------------
__global__ __launch_bounds__(128) void reduce_sq(float scale, int final_out,
                                                 float* __restrict__ out)
{
    __shared__ float4 red[8][16];
    const int ko = blockIdx.x, q = blockIdx.y, t = threadIdx.x;
    const int quad = t & 15, sg = t >> 4;

    const float4* pp = (const float4*)g_p + (size_t)ko * 64 + q * 16 + quad;
    const size_t str = (size_t)KO_ * B_ / 4;

    float4 s = make_float4(0.f, 0.f, 0.f, 0.f);
#pragma unroll 6
    for (int j = 0; j < 18; j++) {
        float4 p = pp[(size_t)(sg * 18 + j) * str];
        s.x += p.x; s.y += p.y; s.z += p.z; s.w += p.w;
    }
    red[sg][quad] = s;
    __syncthreads();

    if (t < 16) {
        float4 a = red[0][t];
#pragma unroll
        for (int g = 1; g < 8; g++) {
            float4 p = red[g][t];
            a.x += p.x; a.y += p.y; a.z += p.z; a.w += p.w;
        }
        a.x *= scale; a.y *= scale; a.z *= scale; a.w *= scale;
        float4 v;
        v.x = a.x * fabsf(a.x) / (1.0f + a.x * a.x);
        v.y = a.y * fabsf(a.y) / (1.0f + a.y * a.y);
        v.z = a.z * fabsf(a.z) / (1.0f + a.z * a.z);
        v.w = a.w * fabsf(a.w) / (1.0f + a.w * a.w);
        if (final_out) {
            const int b0 = q * 64 + t * 4;
            out[(b0 + 0) * KO_ + ko] = v.x;
            out[(b0 + 1) * KO_ + ko] = v.y;
            out[(b0 + 2) * KO_ + ko] = v.z;
            out[(b0 + 3) * KO_ + ko] = v.w;
        } else {
            ((float4*)g_vT)[ko * 64 + q * 16 + t] = v;
        }
    }
}

// ---------------------------------------------------------------------------
// K3: fused a-pass + next s-pass; DRAM (a-dot of n) and L2 (s-accum of n-1)
// streams interleaved in one loop body. CTA = 8 n, 512 thr, v in 160KB smem.
// ---------------------------------------------------------------------------
extern __shared__ float vsm[];   // [KO_][B_]

__global__ __launch_bounds__(512, 1) void fused_as(int first)
{
    __shared__ float wred[16][C_];
    __shared__ float csbuf[2][C_];
    const int t = threadIdx.x;
    const int bq = t & 63, kg = t >> 6, b0 = bq * 4;
    const int wid = t >> 5, lane = t & 31;
    const int n0 = blockIdx.x * NG_;

    for (int j = t; j < KO_ * B_ / 4; j += 512)
        ((float4*)vsm)[j] = ((const float4*)g_vT)[j];
    __syncthreads();

    float4 sp[20];
#pragma unroll
    for (int j = 0; j < 20; j++) sp[j] = make_float4(0.f, 0.f, 0.f, 0.f);

    for (int nn = 0; nn < NG_; nn++) {
        const int n = n0 + nn;
        const float* upn = g_u + (size_t)n * KO_ * B_ + b0;
        const float* upm = upn - (size_t)KO_ * B_;
        const float* cp  = csbuf[(nn - 1) & 1];

        float acc[C_];
#pragma unroll
        for (int k = 0; k < C_; k++) acc[k] = 0.f;

        if (nn == 0) {
#pragma unroll 4
            for (int j = 0; j < 20; j++) {
                const int ko = kg + 8 * j;
                const float4 u = *(const float4*)(upn + (size_t)ko * B_);
                const float4 v = *(const float4*)(vsm + ko * B_ + b0);
                acc[j >> 1] += fmaf(u.x, v.x, fmaf(u.y, v.y, fmaf(u.z, v.z, u.w * v.w)));
            }
        } else {
#pragma unroll 4
            for (int j = 0; j < 20; j++) {
                const int ko = kg + 8 * j;
                const float4 un = *(const float4*)(upn + (size_t)ko * B_);   // DRAM
                const float4 um = *(const float4*)(upm + (size_t)ko * B_);   // L2
                const float4 v  = *(const float4*)(vsm + ko * B_ + b0);
                acc[j >> 1] += fmaf(un.x, v.x, fmaf(un.y, v.y, fmaf(un.z, v.z, un.w * v.w)));
                const float c = cp[j >> 1];
                sp[j].x = fmaf(c, um.x, sp[j].x);
                sp[j].y = fmaf(c, um.y, sp[j].y);
                sp[j].z = fmaf(c, um.z, sp[j].z);
                sp[j].w = fmaf(c, um.w, sp[j].w);
            }
        }
#pragma unroll
        for (int k = 0; k < C_; k++) {
            float a = acc[k];
#pragma unroll
            for (int m = 16; m >= 1; m >>= 1)
                a += __shfl_xor_sync(0xffffffffu, a, m);
            if (lane == 0) wred[wid][k] = a;
        }
        __syncthreads();   // publish wred(n)

        if (wid == 0 && lane < 16) {
            float bn = -1e30f;
            if (lane < C_) {
                float a = 0.f;
#pragma unroll
                for (int w = 0; w < 16; w++) a += wred[w][lane];
                bn = a * (1.0f / (float)B_);
                if (!first) bn += g_bij[n * C_ + lane];
                g_bij[n * C_ + lane] = bn;
            }
            float mx = bn;
#pragma unroll
            for (int m = 8; m >= 1; m >>= 1)
                mx = fmaxf(mx, __shfl_xor_sync(0x0000ffffu, mx, m, 16));
            float e = (lane < C_) ? expf(bn - mx) : 0.f;
            float sm = e;
#pragma unroll
            for (int m = 8; m >= 1; m >>= 1)
                sm += __shfl_xor_sync(0x0000ffffu, sm, m, 16);
            if (lane < C_) csbuf[nn & 1][lane] = e / sm;
        }
        __syncthreads();   // publish csbuf(n)
    }
    // epilogue: s-accum for last n (u hot in L1/L2)
    {
        const float* upm = g_u + (size_t)(n0 + NG_ - 1) * KO_ * B_ + b0;
        const float* cp  = csbuf[(NG_ - 1) & 1];
#pragma unroll 4
        for (int j = 0; j < 20; j++) {
            const int ko = kg + 8 * j;
            const float4 um = *(const float4*)(upm + (size_t)ko * B_);
            const float c = cp[j >> 1];
            sp[j].x = fmaf(c, um.x, sp[j].x);
            sp[j].y = fmaf(c, um.y, sp[j].y);
            sp[j].z = fmaf(c, um.z, sp[j].z);
            sp[j].w = fmaf(c, um.w, sp[j].w);
        }
    }
    float* pp = g_p + (size_t)blockIdx.x * KO_ * B_ + b0;
#pragma unroll
    for (int j = 0; j < 20; j++)
        *(float4*)(pp + (size_t)(kg + 8 * j) * B_) = sp[j];
}

// ---------------------------------------------------------------------------
extern "C" void kernel_launch(void* const* d_in, const int* in_sizes, int n_in,
                              void* d_out, int out_size)
{
    const float* x = (const float*)d_in[0];
    const float* W = (const float*)d_in[1];
    if (in_sizes[0] == N_ * C_ * 16 * IN_) { const float* t = x; x = W; W = t; }
    float* out = (float*)d_out;

    const int vbytes = KO_ * B_ * (int)sizeof(float);
    cudaFuncSetAttribute(fused_as, cudaFuncAttributeMaxDynamicSharedMemorySize, vbytes);

    noop_k<<<1, 32>>>();                               // launch-shift so ncu's
    noop_k<<<1, 32>>>();                               // -s5 captures fused_as
    xpose<<<dim3(N_ * IN_ / 32, B_ / 32), dim3(32, 8)>>>(x);
    uhat_s0<<<dim3(GRID_, 2), 512>>>(W);               // u + s0 partials
    reduce_sq<<<dim3(KO_, 4), 128>>>(0.1f, 0, nullptr);// v0 (c0 = 1/C)
    fused_as<<<GRID_, 512, vbytes>>>(1);               // a0 -> c1 -> s1 partials
    reduce_sq<<<dim3(KO_, 4), 128>>>(1.0f, 0, nullptr);// v1
    fused_as<<<GRID_, 512, vbytes>>>(0);               // a1 -> c2 -> s2 partials
    reduce_sq<<<dim3(KO_, 4), 128>>>(1.0f, 1, out);    // v2 -> d_out
}

// round 9
// speedup vs baseline: 1.4469x; 1.4469x over previous
#include <cuda_runtime.h>
#include <math.h>

#define B_    256
#define N_    1152
#define C_    10
#define IN_   8
#define KO_   160
#define NG_   8                    // n per CTA
#define GRID_ 144                  // N_/NG_

typedef unsigned long long u64;

#define WS2_ELEMS (NG_ * KO_ * IN_)          // 10240 u64 = 80 KB
#define S_DYN_BYTES ((WS2_ELEMS + NG_ * C_) * 8)
#define A_DYN_BYTES (WS2_ELEMS * 8)

// NO g_u! partials g_p[144][ko][b]; xT [(n,i)][b]
__device__ float g_p[(size_t)GRID_ * KO_ * B_];
__device__ float g_xT[(size_t)N_ * IN_ * B_];
__device__ float g_vT[KO_ * B_];
__device__ float g_bij[N_ * C_];
__device__ float g_c[N_ * C_];

// ---- packed f32x2 helpers (sm_100a) --------------------------------------
__device__ __forceinline__ u64 pk(float lo, float hi) {
    u64 d; asm("mov.b64 %0, {%1, %2};" : "=l"(d) : "f"(lo), "f"(hi)); return d;
}
__device__ __forceinline__ void upk(u64 d, float& lo, float& hi) {
    asm("mov.b64 {%0, %1}, %2;" : "=f"(lo), "=f"(hi) : "l"(d));
}
__device__ __forceinline__ u64 fma2(u64 a, u64 b, u64 c) {
    u64 d; asm("fma.rn.f32x2 %0, %1, %2, %3;" : "=l"(d) : "l"(a), "l"(b), "l"(c));
    return d;
}

__global__ void zero_bij() {
    g_bij[blockIdx.x * 256 + threadIdx.x] = 0.f;   // grid 45, 11520 total
}

// ---------------------------------------------------------------------------
// K0: transpose x[b][(n,i)] -> xT[(n,i)][b].
// ---------------------------------------------------------------------------
__global__ __launch_bounds__(256) void xpose(const float* __restrict__ x)
{
    __shared__ float tile[32][33];
    const int cb = blockIdx.x * 32, bb = blockIdx.y * 32;
    const int tx = threadIdx.x, ty = threadIdx.y;
#pragma unroll
    for (int k = 0; k < 4; k++)
        tile[ty + 8 * k][tx] = x[(size_t)(bb + ty + 8 * k) * (N_ * IN_) + cb + tx];
    __syncthreads();
#pragma unroll
    for (int k = 0; k < 4; k++)
        g_xT[(size_t)(cb + ty + 8 * k) * B_ + bb + tx] = tile[tx][ty + 8 * k];
}

extern __shared__ u64 dynsm[];   // s_gemm: [Ws2 | cs2]; a_gemm: [Ws2]

// ---------------------------------------------------------------------------
// S-GEMM: p[slab][ko][b] = sum_{n in slab} c[n,k] * (sum_i xT[(n,i)][b] W[n,ko,i])
// u rebuilt on the fly; W pre-packed {w,w} in dyn smem (LDS.64 warp-broadcast).
// 512 thr = 64 b-quads x 8 kg; ko in 2 sequential halves (reg pressure).
// ---------------------------------------------------------------------------
__global__ __launch_bounds__(512, 1) void s_gemm(const float* __restrict__ W,
                                                 int uniform)
{
    u64* Ws2 = dynsm;                 // 80 KB
    u64* cs2 = dynsm + WS2_ELEMS;     // 640 B
    const int t = threadIdx.x, bq = t & 63, kg = t >> 6;
    const int n0 = blockIdx.x * NG_;

    for (int j = t; j < WS2_ELEMS; j += 512) {
        float w = W[(size_t)(n0 + j / 1280) * 1280 + (j % 1280)];
        Ws2[j] = pk(w, w);
    }
    if (t < NG_ * C_) {
        float c = uniform ? 0.1f : g_c[n0 * C_ + t];
        cs2[t] = pk(c, c);
    }
    __syncthreads();

    for (int koh = 0; koh < 2; koh++) {
        u64 sp[10][2];
#pragma unroll
        for (int j = 0; j < 10; j++) { sp[j][0] = 0ull; sp[j][1] = 0ull; }

        for (int nn = 0; nn < NG_; nn++) {
            const int n = n0 + nn;
            u64 xp[IN_][2];
#pragma unroll
            for (int i = 0; i < IN_; i++) {
                float4 xv = __ldg((const float4*)(g_xT + ((size_t)n * IN_ + i) * B_) + bq);
                xp[i][0] = pk(xv.x, xv.y);
                xp[i][1] = pk(xv.z, xv.w);
            }
            const u64* wn = Ws2 + nn * (KO_ * IN_) + (koh * 80 + kg) * IN_;
            const u64* cn = cs2 + nn * C_ + koh * 5;
#pragma unroll
            for (int j = 0; j < 10; j++) {
                const u64* wj = wn + j * 64;           // ko = koh*80 + kg + 8j
                u64 u0 = 0ull, u1 = 0ull;
#pragma unroll
                for (int i = 0; i < IN_; i++) {
                    const u64 wv = wj[i];
                    u0 = fma2(wv, xp[i][0], u0);
                    u1 = fma2(wv, xp[i][1], u1);
                }
                const u64 c2 = cn[j >> 1];             // k = koh*5 + (j>>1)
                sp[j][0] = fma2(c2, u0, sp[j][0]);
                sp[j][1] = fma2(c2, u1, sp[j][1]);
            }
        }
#pragma unroll
        for (int j = 0; j < 10; j++) {
            const int ko = koh * 80 + kg + 8 * j;
            u64* op = (u64*)(g_p + ((size_t)blockIdx.x * KO_ + ko) * B_ + bq * 4);
            op[0] = sp[j][0];
            op[1] = sp[j][1];
        }
    }
}

// ---------------------------------------------------------------------------
// A-GEMM: a[n,k] = (1/B) sum_{b,o} u(n,ko,b)*v(ko,b), u on the fly;
// fused bij update + softmax -> g_c[n]. v read from global (L1-resident).
// ---------------------------------------------------------------------------
__global__ __launch_bounds__(512, 1) void a_gemm(const float* __restrict__ W)
{
    u64* Ws2 = dynsm;                 // 80 KB
    __shared__ float wred[16][C_];
    const int t = threadIdx.x, bq = t & 63, kg = t >> 6;
    const int wid = t >> 5, lane = t & 31;
    const int n0 = blockIdx.x * NG_;

    for (int j = t; j < WS2_ELEMS; j += 512) {
        float w = W[(size_t)(n0 + j / 1280) * 1280 + (j % 1280)];
        Ws2[j] = pk(w, w);
    }
    __syncthreads();

    for (int nn = 0; nn < NG_; nn++) {
        const int n = n0 + nn;
        u64 xp[IN_][2];
#pragma unroll
        for (int i = 0; i < IN_; i++) {
            float4 xv = __ldg((const float4*)(g_xT + ((size_t)n * IN_ + i) * B_) + bq);
            xp[i][0] = pk(xv.x, xv.y);
            xp[i][1] = pk(xv.z, xv.w);
        }
        const u64* wn = Ws2 + nn * (KO_ * IN_) + kg * IN_;

        u64 acc2[C_];
#pragma unroll
        for (int k = 0; k < C_; k++) acc2[k] = 0ull;
#pragma unroll
        for (int j = 0; j < 20; j++) {
            const u64* wj = wn + j * 64;               // ko = kg + 8j
            u64 u0 = 0ull, u1 = 0ull;
#pragma unroll
            for (int i = 0; i < IN_; i++) {
                const u64 wv = wj[i];
                u0 = fma2(wv, xp[i][0], u0);
                u1 = fma2(wv, xp[i][1], u1);
            }
            float4 v4 = __ldg((const float4*)(g_vT + (size_t)(kg + 8 * j) * B_) + bq);
            acc2[j >> 1] = fma2(u0, pk(v4.x, v4.y), acc2[j >> 1]);
            acc2[j >> 1] = fma2(u1, pk(v4.z, v4.w), acc2[j >> 1]);
        }
#pragma unroll
        for (int k = 0; k < C_; k++) {
            float lo, hi;  upk(acc2[k], lo, hi);
            float a = lo + hi;
#pragma unroll
            for (int m = 16; m >= 1; m >>= 1)
                a += __shfl_xor_sync(0xffffffffu, a, m);
            if (lane == 0) wred[wid][k] = a;
        }
        __syncthreads();

        if (wid == 0 && lane < 16) {
            float bn = -1e30f;
            if (lane < C_) {
                float a = 0.f;
#pragma unroll
                for (int w = 0; w < 16; w++) a += wred[w][lane];
                bn = a * (1.0f / (float)B_) + g_bij[n * C_ + lane];
                g_bij[n * C_ + lane] = bn;
            }
            float mx = bn;
#pragma unroll
            for (int m = 8; m >= 1; m >>= 1)
                mx = fmaxf(mx, __shfl_xor_sync(0x0000ffffu, mx, m, 16));
            float e = (lane < C_) ? expf(bn - mx) : 0.f;
            float sm = e;
#pragma unroll
            for (int m = 8; m >= 1; m >>= 1)
                sm += __shfl_xor_sync(0x0000ffffu, sm, m, 16);
            if (lane < C_) g_c[n * C_ + lane] = e / sm;
        }
        __syncthreads();
    }
}

// ---------------------------------------------------------------------------
// Reduce 144 slabs + squash. Grid (160 ko, 4 b-quarters), 128 thr.
// ---------------------------------------------------------------------------
__global__ __launch_bounds__(128) void reduce_sq(int final_out, float* __restrict__ out)
{
    __shared__ float4 red[8][16];
    const int ko = blockIdx.x, q = blockIdx.y, t = threadIdx.x;
    const int quad = t & 15, sg = t >> 4;

    const float4* pp = (const float4*)g_p + (size_t)ko * 64 + q * 16 + quad;
    const size_t str = (size_t)KO_ * B_ / 4;

    float4 s = make_float4(0.f, 0.f, 0.f, 0.f);
#pragma unroll 6
    for (int j = 0; j < 18; j++) {
        float4 p = pp[(size_t)(sg * 18 + j) * str];
        s.x += p.x; s.y += p.y; s.z += p.z; s.w += p.w;
    }
    red[sg][quad] = s;
    __syncthreads();

    if (t < 16) {
        float4 a = red[0][t];
#pragma unroll
        for (int g = 1; g < 8; g++) {
            float4 p = red[g][t];
            a.x += p.x; a.y += p.y; a.z += p.z; a.w += p.w;
        }
        float4 v;
        v.x = a.x * fabsf(a.x) / (1.0f + a.x * a.x);
        v.y = a.y * fabsf(a.y) / (1.0f + a.y * a.y);
        v.z = a.z * fabsf(a.z) / (1.0f + a.z * a.z);
        v.w = a.w * fabsf(a.w) / (1.0f + a.w * a.w);
        if (final_out) {
            const int b0 = q * 64 + t * 4;
            out[(b0 + 0) * KO_ + ko] = v.x;
            out[(b0 + 1) * KO_ + ko] = v.y;
            out[(b0 + 2) * KO_ + ko] = v.z;
            out[(b0 + 3) * KO_ + ko] = v.w;
        } else {
            ((float4*)g_vT)[ko * 64 + q * 16 + t] = v;
        }
    }
}

// ---------------------------------------------------------------------------
extern "C" void kernel_launch(void* const* d_in, const int* in_sizes, int n_in,
                              void* d_out, int out_size)
{
    const float* x = (const float*)d_in[0];
    const float* W = (const float*)d_in[1];
    if (in_sizes[0] == N_ * C_ * 16 * IN_) { const float* t = x; x = W; W = t; }
    float* out = (float*)d_out;

    cudaFuncSetAttribute(s_gemm, cudaFuncAttributeMaxDynamicSharedMemorySize, S_DYN_BYTES);
    cudaFuncSetAttribute(a_gemm, cudaFuncAttributeMaxDynamicSharedMemorySize, A_DYN_BYTES);

    zero_bij<<<45, 256>>>();                                  // #1 (ncu shift)
    xpose<<<dim3(N_ * IN_ / 32, B_ / 32), dim3(32, 8)>>>(x);  // #2
    s_gemm<<<GRID_, 512, S_DYN_BYTES>>>(W, 1);                // #3  s0 (c=1/C)
    reduce_sq<<<dim3(KO_, 4), 128>>>(0, nullptr);             // #4  v0
    a_gemm<<<GRID_, 512, A_DYN_BYTES>>>(W);                   // #5  c1
    s_gemm<<<GRID_, 512, S_DYN_BYTES>>>(W, 0);                // #6  s1  <- ncu
    reduce_sq<<<dim3(KO_, 4), 128>>>(0, nullptr);             // #7  v1
    a_gemm<<<GRID_, 512, A_DYN_BYTES>>>(W);                   // #8  c2
    s_gemm<<<GRID_, 512, S_DYN_BYTES>>>(W, 0);                // #9  s2
    reduce_sq<<<dim3(KO_, 4), 128>>>(1, out);                 // #10 v2 -> d_out
}

// round 10
// speedup vs baseline: 1.6908x; 1.1685x over previous
#include <cuda_runtime.h>
#include <math.h>

#define B_    256
#define N_    1152
#define C_    10
#define IN_   8
#define KO_   160
#define NG_   8                    // n per CTA
#define GRID_ 144                  // N_/NG_

typedef unsigned long long u64;

#define WS2_ELEMS (NG_ * KO_ * IN_)          // 10240 u64 = 80 KB
#define DYN_BYTES (WS2_ELEMS * 8)

__device__ float g_p[(size_t)GRID_ * KO_ * B_];
__device__ float g_xT[(size_t)N_ * IN_ * B_];
__device__ float g_vT[KO_ * B_];
__device__ float g_bij[N_ * C_];
__device__ float g_c[N_ * C_];

// ---- packed f32x2 helpers --------------------------------------------------
__device__ __forceinline__ u64 pk(float lo, float hi) {
    u64 d; asm("mov.b64 %0, {%1, %2};" : "=l"(d) : "f"(lo), "f"(hi)); return d;
}
__device__ __forceinline__ void upk(u64 d, float& lo, float& hi) {
    asm("mov.b64 {%0, %1}, %2;" : "=f"(lo), "=f"(hi) : "l"(d));
}
__device__ __forceinline__ u64 fma2(u64 a, u64 b, u64 c) {
    u64 d; asm("fma.rn.f32x2 %0, %1, %2, %3;" : "=l"(d) : "l"(a), "l"(b), "l"(c));
    return d;
}

__global__ void zero_bij() {
    g_bij[blockIdx.x * 256 + threadIdx.x] = 0.f;   // grid 45
}

// ---------------------------------------------------------------------------
// K0: transpose x[b][(n,i)] -> xT[(n,i)][b].
// ---------------------------------------------------------------------------
__global__ __launch_bounds__(256) void xpose(const float* __restrict__ x)
{
    __shared__ float tile[32][33];
    const int cb = blockIdx.x * 32, bb = blockIdx.y * 32;
    const int tx = threadIdx.x, ty = threadIdx.y;
#pragma unroll
    for (int k = 0; k < 4; k++)
        tile[ty + 8 * k][tx] = x[(size_t)(bb + ty + 8 * k) * (N_ * IN_) + cb + tx];
    __syncthreads();
#pragma unroll
    for (int k = 0; k < 4; k++)
        g_xT[(size_t)(cb + ty + 8 * k) * B_ + bb + tx] = tile[tx][ty + 8 * k];
}

extern __shared__ u64 dynsm[];   // Ws2 / Wc2: 80 KB

// ---------------------------------------------------------------------------
// S-pass: p[slab][ko][b] = sum_{n,i} Wc[n,ko,i]*xT[(n,i)][b],
// where Wc = c[n,k]*W folded in the prologue. u never materialized.
// 512 thr = 64 bq x 8 kg; ko in 2 halves for reg pressure.
// ---------------------------------------------------------------------------
__global__ __launch_bounds__(512, 1) void s_fold(const float* __restrict__ W,
                                                 int uniform)
{
    u64* Wc2 = dynsm;
    const int t = threadIdx.x, bq = t & 63, kg = t >> 6;
    const int n0 = blockIdx.x * NG_;

    for (int j = t; j < WS2_ELEMS; j += 512) {
        const int nl = j >> 10 ? j / 1280 : j / 1280;   // n_local
        const int rem = j - nl * 1280;
        const int ko = rem >> 3;
        float c = uniform ? 0.1f : __ldg(&g_c[(n0 + nl) * C_ + (ko >> 4)]);
        float w = __ldg(&W[(size_t)(n0 + nl) * 1280 + rem]) * c;
        Wc2[j] = pk(w, w);
    }
    __syncthreads();

    for (int koh = 0; koh < 2; koh++) {
        u64 sp[10][2];
#pragma unroll
        for (int j = 0; j < 10; j++) { sp[j][0] = 0ull; sp[j][1] = 0ull; }

        for (int nn = 0; nn < NG_; nn++) {
            const int n = n0 + nn;
            u64 xp[IN_][2];
#pragma unroll
            for (int i = 0; i < IN_; i++) {
                float4 xv = __ldg((const float4*)(g_xT + ((size_t)n * IN_ + i) * B_) + bq);
                xp[i][0] = pk(xv.x, xv.y);
                xp[i][1] = pk(xv.z, xv.w);
            }
            const u64* wn = Wc2 + nn * (KO_ * IN_) + (koh * 80 + kg) * IN_;
#pragma unroll
            for (int j = 0; j < 10; j++) {
                const u64* wj = wn + j * 64;           // ko = koh*80 + kg + 8j
#pragma unroll
                for (int i = 0; i < IN_; i++) {
                    const u64 wv = wj[i];
                    sp[j][0] = fma2(wv, xp[i][0], sp[j][0]);
                    sp[j][1] = fma2(wv, xp[i][1], sp[j][1]);
                }
            }
        }
#pragma unroll
        for (int j = 0; j < 10; j++) {
            const int ko = koh * 80 + kg + 8 * j;
            u64* op = (u64*)(g_p + ((size_t)blockIdx.x * KO_ + ko) * B_ + bq * 4);
            op[0] = sp[j][0];
            op[1] = sp[j][1];
        }
    }
}

// ---------------------------------------------------------------------------
// A-pass: a[n,k] = (1/B) sum_{b,o} u*v (u on the fly); batched softmaxes:
// no syncs inside the nn loop; afterwards 8 warps do 8 per-n softmaxes.
// ---------------------------------------------------------------------------
__global__ __launch_bounds__(512, 1) void a_gemm(const float* __restrict__ W)
{
    u64* Ws2 = dynsm;
    __shared__ float wredN[NG_][16][C_];    // 5 KB
    const int t = threadIdx.x, bq = t & 63, kg = t >> 6;
    const int wid = t >> 5, lane = t & 31;
    const int n0 = blockIdx.x * NG_;

    for (int j = t; j < WS2_ELEMS; j += 512) {
        float w = __ldg(&W[(size_t)(n0 + j / 1280) * 1280 + (j % 1280)]);
        Ws2[j] = pk(w, w);
    }
    __syncthreads();

    for (int nn = 0; nn < NG_; nn++) {
        const int n = n0 + nn;
        u64 xp[IN_][2];
#pragma unroll
        for (int i = 0; i < IN_; i++) {
            float4 xv = __ldg((const float4*)(g_xT + ((size_t)n * IN_ + i) * B_) + bq);
            xp[i][0] = pk(xv.x, xv.y);
            xp[i][1] = pk(xv.z, xv.w);
        }
        const u64* wn = Ws2 + nn * (KO_ * IN_) + kg * IN_;

        u64 acc2[C_];
#pragma unroll
        for (int k = 0; k < C_; k++) acc2[k] = 0ull;
#pragma unroll
        for (int j = 0; j < 20; j++) {
            const u64* wj = wn + j * 64;               // ko = kg + 8j
            u64 u0 = 0ull, u1 = 0ull;
#pragma unroll
            for (int i = 0; i < IN_; i++) {
                const u64 wv = wj[i];
                u0 = fma2(wv, xp[i][0], u0);
                u1 = fma2(wv, xp[i][1], u1);
            }
            float4 v4 = __ldg((const float4*)(g_vT + (size_t)(kg + 8 * j) * B_) + bq);
            acc2[j >> 1] = fma2(u0, pk(v4.x, v4.y), acc2[j >> 1]);
            acc2[j >> 1] = fma2(u1, pk(v4.z, v4.w), acc2[j >> 1]);
        }
#pragma unroll
        for (int k = 0; k < C_; k++) {
            float lo, hi;  upk(acc2[k], lo, hi);
            float a = lo + hi;
#pragma unroll
            for (int m = 16; m >= 1; m >>= 1)
                a += __shfl_xor_sync(0xffffffffu, a, m);
            if (lane == 0) wredN[nn][wid][k] = a;
        }
        // no __syncthreads: each (nn, wid) cell written once, read after barrier
    }
    __syncthreads();

    if (wid < NG_ && lane < 16) {    // warp wid handles n = n0 + wid
        const int n = n0 + wid;
        float bn = -1e30f;
        if (lane < C_) {
            float a = 0.f;
#pragma unroll
            for (int w = 0; w < 16; w++) a += wredN[wid][w][lane];
            bn = a * (1.0f / (float)B_) + g_bij[n * C_ + lane];
            g_bij[n * C_ + lane] = bn;
        }
        float mx = bn;
#pragma unroll
        for (int m = 8; m >= 1; m >>= 1)
            mx = fmaxf(mx, __shfl_xor_sync(0x0000ffffu, mx, m, 16));
        float e = (lane < C_) ? expf(bn - mx) : 0.f;
        float sm = e;
#pragma unroll
        for (int m = 8; m >= 1; m >>= 1)
            sm += __shfl_xor_sync(0x0000ffffu, sm, m, 16);
        if (lane < C_) g_c[n * C_ + lane] = e / sm;
    }
}

// ---------------------------------------------------------------------------
// Reduce 144 slabs + squash. Grid (160 ko, 4 b-quarters), 256 thr
// = 16 b-quads x 16 slab-groups (9 slabs each). 164k threads resident.
// ---------------------------------------------------------------------------
__global__ __launch_bounds__(256) void reduce_sq(int final_out, float* __restrict__ out)
{
    __shared__ float4 red[16][16];
    const int ko = blockIdx.x, q = blockIdx.y, t = threadIdx.x;
    const int quad = t & 15, sg = t >> 4;

    const float4* pp = (const float4*)g_p + (size_t)ko * 64 + q * 16 + quad;
    const size_t str = (size_t)KO_ * B_ / 4;

    float4 s = make_float4(0.f, 0.f, 0.f, 0.f);
#pragma unroll
    for (int j = 0; j < 9; j++) {
        float4 p = pp[(size_t)(sg * 9 + j) * str];
        s.x += p.x; s.y += p.y; s.z += p.z; s.w += p.w;
    }
    red[sg][quad] = s;
    __syncthreads();

    if (t < 16) {
        float4 a = red[0][t];
#pragma unroll
        for (int g = 1; g < 16; g++) {
            float4 p = red[g][t];
            a.x += p.x; a.y += p.y; a.z += p.z; a.w += p.w;
        }
        float4 v;
        v.x = a.x * fabsf(a.x) / (1.0f + a.x * a.x);
        v.y = a.y * fabsf(a.y) / (1.0f + a.y * a.y);
        v.z = a.z * fabsf(a.z) / (1.0f + a.z * a.z);
        v.w = a.w * fabsf(a.w) / (1.0f + a.w * a.w);
        if (final_out) {
            const int b0 = q * 64 + t * 4;
            out[(b0 + 0) * KO_ + ko] = v.x;
            out[(b0 + 1) * KO_ + ko] = v.y;
            out[(b0 + 2) * KO_ + ko] = v.z;
            out[(b0 + 3) * KO_ + ko] = v.w;
        } else {
            ((float4*)g_vT)[ko * 64 + q * 16 + t] = v;
        }
    }
}

// ---------------------------------------------------------------------------
extern "C" void kernel_launch(void* const* d_in, const int* in_sizes, int n_in,
                              void* d_out, int out_size)
{
    const float* x = (const float*)d_in[0];
    const float* W = (const float*)d_in[1];
    if (in_sizes[0] == N_ * C_ * 16 * IN_) { const float* t = x; x = W; W = t; }
    float* out = (float*)d_out;

    cudaFuncSetAttribute(s_fold, cudaFuncAttributeMaxDynamicSharedMemorySize, DYN_BYTES);
    cudaFuncSetAttribute(a_gemm, cudaFuncAttributeMaxDynamicSharedMemorySize, DYN_BYTES);

    zero_bij<<<45, 256>>>();                                  // #1
    xpose<<<dim3(N_ * IN_ / 32, B_ / 32), dim3(32, 8)>>>(x);  // #2
    s_fold<<<GRID_, 512, DYN_BYTES>>>(W, 1);                  // #3  s0 (c=1/C)
    reduce_sq<<<dim3(KO_, 4), 256>>>(0, nullptr);             // #4  v0
    a_gemm<<<GRID_, 512, DYN_BYTES>>>(W);                     // #5  c1
    s_fold<<<GRID_, 512, DYN_BYTES>>>(W, 0);                  // #6  s1
    reduce_sq<<<dim3(KO_, 4), 256>>>(0, nullptr);             // #7  v1
    a_gemm<<<GRID_, 512, DYN_BYTES>>>(W);                     // #8  c2
    s_fold<<<GRID_, 512, DYN_BYTES>>>(W, 0);                  // #9  s2
    reduce_sq<<<dim3(KO_, 4), 256>>>(1, out);                 // #10 v2 -> d_out
}

// round 11
// speedup vs baseline: 1.7917x; 1.0597x over previous
#include <cuda_runtime.h>
#include <math.h>

#define B_    256
#define N_    1152
#define C_    10
#define IN_   8
#define KO_   160
#define NG_   8                    // n per CTA
#define GRID_ 144                  // N_/NG_

typedef unsigned long long u64;

#define WS2_ELEMS (NG_ * KO_ * IN_)          // 10240 u64 = 80 KB
#define DYN_BYTES (WS2_ELEMS * 8)

// partials layout [ko][slab][b]
__device__ float g_p[(size_t)KO_ * GRID_ * B_];
__device__ float g_xT[(size_t)N_ * IN_ * B_];
__device__ float g_vT[KO_ * B_];
__device__ float g_bij[N_ * C_];

// ---- packed f32x2 helpers --------------------------------------------------
__device__ __forceinline__ u64 pk(float lo, float hi) {
    u64 d; asm("mov.b64 %0, {%1, %2};" : "=l"(d) : "f"(lo), "f"(hi)); return d;
}
__device__ __forceinline__ void upk(u64 d, float& lo, float& hi) {
    asm("mov.b64 {%0, %1}, %2;" : "=f"(lo), "=f"(hi) : "l"(d));
}
__device__ __forceinline__ u64 fma2(u64 a, u64 b, u64 c) {
    u64 d; asm("fma.rn.f32x2 %0, %1, %2, %3;" : "=l"(d) : "l"(a), "l"(b), "l"(c));
    return d;
}

__global__ void noop_k() {}
__global__ void zero_bij() { g_bij[blockIdx.x * 256 + threadIdx.x] = 0.f; }

// ---------------------------------------------------------------------------
// K0: transpose x[b][(n,i)] -> xT[(n,i)][b].
// ---------------------------------------------------------------------------
__global__ __launch_bounds__(256) void xpose(const float* __restrict__ x)
{
    __shared__ float tile[32][33];
    const int cb = blockIdx.x * 32, bb = blockIdx.y * 32;
    const int tx = threadIdx.x, ty = threadIdx.y;
#pragma unroll
    for (int k = 0; k < 4; k++)
        tile[ty + 8 * k][tx] = x[(size_t)(bb + ty + 8 * k) * (N_ * IN_) + cb + tx];
    __syncthreads();
#pragma unroll
    for (int k = 0; k < 4; k++)
        g_xT[(size_t)(cb + ty + 8 * k) * B_ + bb + tx] = tile[tx][ty + 8 * k];
}

extern __shared__ u64 dynsm[];   // packed W: 80 KB

// s-mainloop shared by s_fold and as_fused: Wc2 already has c folded in.
__device__ __forceinline__ void s_mainloop(const u64* Wc2, int n0, int slab,
                                           int bq, int kg)
{
    for (int koh = 0; koh < 2; koh++) {
        u64 sp[10][2];
#pragma unroll
        for (int j = 0; j < 10; j++) { sp[j][0] = 0ull; sp[j][1] = 0ull; }

        for (int nn = 0; nn < NG_; nn++) {
            const int n = n0 + nn;
            u64 xp[IN_][2];
#pragma unroll
            for (int i = 0; i < IN_; i++) {
                float4 xv = __ldg((const float4*)(g_xT + ((size_t)n * IN_ + i) * B_) + bq);
                xp[i][0] = pk(xv.x, xv.y);
                xp[i][1] = pk(xv.z, xv.w);
            }
            const u64* wn = Wc2 + nn * (KO_ * IN_) + (koh * 80 + kg) * IN_;
#pragma unroll
            for (int j = 0; j < 10; j++) {
                const u64* wj = wn + j * 64;
#pragma unroll
                for (int i = 0; i < IN_; i++) {
                    const u64 wv = wj[i];
                    sp[j][0] = fma2(wv, xp[i][0], sp[j][0]);
                    sp[j][1] = fma2(wv, xp[i][1], sp[j][1]);
                }
            }
        }
#pragma unroll
        for (int j = 0; j < 10; j++) {
            const int ko = koh * 80 + kg + 8 * j;
            u64* op = (u64*)(g_p + ((size_t)ko * GRID_ + slab) * B_ + bq * 4);
            op[0] = sp[j][0];
            op[1] = sp[j][1];
        }
    }
}

// ---------------------------------------------------------------------------
// S0: uniform c = 1/C folded into W at staging.
// ---------------------------------------------------------------------------
__global__ __launch_bounds__(512, 1) void s_fold(const float* __restrict__ W)
{
    u64* Wc2 = dynsm;
    const int t = threadIdx.x, bq = t & 63, kg = t >> 6;
    const int n0 = blockIdx.x * NG_;

    for (int j = t; j < WS2_ELEMS; j += 512) {
        float w = __ldg(&W[(size_t)(n0 + j / 1280) * 1280 + (j % 1280)]) * 0.1f;
        Wc2[j] = pk(w, w);
    }
    __syncthreads();
    s_mainloop(Wc2, n0, blockIdx.x, bq, kg);
}

// ---------------------------------------------------------------------------
// AS-fused: a-dots (u on the fly) -> batched softmax -> rescale smem W by c
// in place -> s-mainloop. One kernel per routing iteration.
// ---------------------------------------------------------------------------
__global__ __launch_bounds__(512, 1) void as_fused(const float* __restrict__ W)
{
    u64* Ws2 = dynsm;
    __shared__ float wredN[NG_][16][C_];
    __shared__ float cs[NG_][C_];
    const int t = threadIdx.x, bq = t & 63, kg = t >> 6;
    const int wid = t >> 5, lane = t & 31;
    const int n0 = blockIdx.x * NG_;

    for (int j = t; j < WS2_ELEMS; j += 512) {
        float w = __ldg(&W[(size_t)(n0 + j / 1280) * 1280 + (j % 1280)]);
        Ws2[j] = pk(w, w);
    }
    __syncthreads();

    // ---- a-phase ----
    for (int nn = 0; nn < NG_; nn++) {
        const int n = n0 + nn;
        u64 xp[IN_][2];
#pragma unroll
        for (int i = 0; i < IN_; i++) {
            float4 xv = __ldg((const float4*)(g_xT + ((size_t)n * IN_ + i) * B_) + bq);
            xp[i][0] = pk(xv.x, xv.y);
            xp[i][1] = pk(xv.z, xv.w);
        }
        const u64* wn = Ws2 + nn * (KO_ * IN_) + kg * IN_;

        u64 acc2[C_];
#pragma unroll
        for (int k = 0; k < C_; k++) acc2[k] = 0ull;
#pragma unroll
        for (int j = 0; j < 20; j++) {
            const u64* wj = wn + j * 64;               // ko = kg + 8j
            u64 u0 = 0ull, u1 = 0ull;
#pragma unroll
            for (int i = 0; i < IN_; i++) {
                const u64 wv = wj[i];
                u0 = fma2(wv, xp[i][0], u0);
                u1 = fma2(wv, xp[i][1], u1);
            }
            float4 v4 = __ldg((const float4*)(g_vT + (size_t)(kg + 8 * j) * B_) + bq);
            acc2[j >> 1] = fma2(u0, pk(v4.x, v4.y), acc2[j >> 1]);
            acc2[j >> 1] = fma2(u1, pk(v4.z, v4.w), acc2[j >> 1]);
        }
#pragma unroll
        for (int k = 0; k < C_; k++) {
            float lo, hi;  upk(acc2[k], lo, hi);
            float a = lo + hi;
#pragma unroll
            for (int m = 16; m >= 1; m >>= 1)
                a += __shfl_xor_sync(0xffffffffu, a, m);
            if (lane == 0) wredN[nn][wid][k] = a;
        }
    }
    __syncthreads();

    // ---- batched softmax: warp wid handles n0+wid ----
    if (wid < NG_ && lane < 16) {
        const int n = n0 + wid;
        float bn = -1e30f;
        if (lane < C_) {
            float a = 0.f;
#pragma unroll
            for (int w = 0; w < 16; w++) a += wredN[wid][w][lane];
            bn = a * (1.0f / (float)B_) + g_bij[n * C_ + lane];
            g_bij[n * C_ + lane] = bn;
        }
        float mx = bn;
#pragma unroll
        for (int m = 8; m >= 1; m >>= 1)
            mx = fmaxf(mx, __shfl_xor_sync(0x0000ffffu, mx, m, 16));
        float e = (lane < C_) ? expf(bn - mx) : 0.f;
        float sm = e;
#pragma unroll
        for (int m = 8; m >= 1; m >>= 1)
            sm += __shfl_xor_sync(0x0000ffffu, sm, m, 16);
        if (lane < C_) cs[wid][lane] = e / sm;
    }
    __syncthreads();

    // ---- rescale W in place: Wc = c[n,k] * W ----
    for (int j = t; j < WS2_ELEMS; j += 512) {
        const int nl = j / 1280, rem = j - nl * 1280;
        const int k = rem >> 7;            // ko>>4 = (rem>>3)>>4
        float lo, hi; upk(Ws2[j], lo, hi);
        float w = lo * cs[nl][k];
        Ws2[j] = pk(w, w);
    }
    __syncthreads();

    // ---- s-phase ----
    s_mainloop(Ws2, n0, blockIdx.x, bq, kg);
}

// ---------------------------------------------------------------------------
// Reduce 144 slabs ([ko][slab][b] layout: 1KB strides) + squash.
// Grid (160 ko, 4 bq), 256 thr = 16 quads x 16 slab-groups (9 each).
// ---------------------------------------------------------------------------
__global__ __launch_bounds__(256) void reduce_sq(int final_out, float* __restrict__ out)
{
    __shared__ float4 red[16][16];
    const int ko = blockIdx.x, q = blockIdx.y, t = threadIdx.x;
    const int quad = t & 15, sg = t >> 4;

    const float4* pp = (const float4*)(g_p + (size_t)ko * GRID_ * B_) + q * 16 + quad;
    const size_t str = B_ / 4;   // slab stride in float4

    float4 s = make_float4(0.f, 0.f, 0.f, 0.f);
#pragma unroll
    for (int j = 0; j < 9; j++) {
        float4 p = pp[(size_t)(sg * 9 + j) * str];
        s.x += p.x; s.y += p.y; s.z += p.z; s.w += p.w;
    }
    red[sg][quad] = s;
    __syncthreads();

    if (t < 16) {
        float4 a = red[0][t];
#pragma unroll
        for (int g = 1; g < 16; g++) {
            float4 p = red[g][t];
            a.x += p.x; a.y += p.y; a.z += p.z; a.w += p.w;
        }
        float4 v;
        v.x = a.x * fabsf(a.x) / (1.0f + a.x * a.x);
        v.y = a.y * fabsf(a.y) / (1.0f + a.y * a.y);
        v.z = a.z * fabsf(a.z) / (1.0f + a.z * a.z);
        v.w = a.w * fabsf(a.w) / (1.0f + a.w * a.w);
        if (final_out) {
            const int b0 = q * 64 + t * 4;
            out[(b0 + 0) * KO_ + ko] = v.x;
            out[(b0 + 1) * KO_ + ko] = v.y;
            out[(b0 + 2) * KO_ + ko] = v.z;
            out[(b0 + 3) * KO_ + ko] = v.w;
        } else {
            ((float4*)g_vT)[ko * 64 + q * 16 + t] = v;
        }
    }
}

// ---------------------------------------------------------------------------
extern "C" void kernel_launch(void* const* d_in, const int* in_sizes, int n_in,
                              void* d_out, int out_size)
{
    const float* x = (const float*)d_in[0];
    const float* W = (const float*)d_in[1];
    if (in_sizes[0] == N_ * C_ * 16 * IN_) { const float* t = x; x = W; W = t; }
    float* out = (float*)d_out;

    cudaFuncSetAttribute(s_fold,   cudaFuncAttributeMaxDynamicSharedMemorySize, DYN_BYTES);
    cudaFuncSetAttribute(as_fused, cudaFuncAttributeMaxDynamicSharedMemorySize, DYN_BYTES);

    zero_bij<<<45, 256>>>();                                  // #0
    xpose<<<dim3(N_ * IN_ / 32, B_ / 32), dim3(32, 8)>>>(x);  // #1
    noop_k<<<1, 32>>>();                                      // #2 (capture pad)
    s_fold<<<GRID_, 512, DYN_BYTES>>>(W);                     // #3  <- ncu slot
    reduce_sq<<<dim3(KO_, 4), 256>>>(0, nullptr);             // #4  v0
    as_fused<<<GRID_, 512, DYN_BYTES>>>(W);                   // #5  a0+s1
    reduce_sq<<<dim3(KO_, 4), 256>>>(0, nullptr);             // #6  v1
    as_fused<<<GRID_, 512, DYN_BYTES>>>(W);                   // #7  a1+s2
    reduce_sq<<<dim3(KO_, 4), 256>>>(1, out);                 // #8  v2 -> d_out
}